// round 17
// baseline (speedup 1.0000x reference)
#include <cuda_runtime.h>
#include <math.h>
#include <stdint.h>

// Problem constants
constexpr int BATCH = 4;
constexpr int SEQ   = 2048;
constexpr int DIM   = 768;
constexpr int HEADS = 12;
constexpr int DH    = 64;              // head dim
constexpr int MROWS = BATCH * SEQ;     // 8192
constexpr int KP    = DIM / 2;         // 384 k-pairs per row
constexpr float SCALE = 0.03608439182435161f;  // 768^-0.5

// ---------------------------------------------------------------------------
// Scratch: EXACTLY 96 MiB of __device__ globals (4 x 24 MiB), matching every
// passing round. g_q/g_k: tf32 words ([b,h,n,d]); g_v: tf32 TRANSPOSED
// ([b,h,d,n]); g_attp: split-bf16 packed attention output (out-GEMM A).
// ---------------------------------------------------------------------------
__device__ __align__(16) uint32_t g_q[(size_t)BATCH * HEADS * SEQ * DH];
__device__ __align__(16) uint32_t g_k[(size_t)BATCH * HEADS * SEQ * DH];
__device__ __align__(16) uint32_t g_v[(size_t)BATCH * HEADS * SEQ * DH];
__device__ __align__(16) uint2    g_attp[(size_t)MROWS * KP];

// ---------------------------------------------------------------------------
// Conversion helpers
// ---------------------------------------------------------------------------
__device__ __forceinline__ uint32_t cvt_tf32(float f) {
    uint32_t r;
    asm("cvt.rna.tf32.f32 %0, %1;" : "=r"(r) : "f"(f));
    return r;
}

// pack two floats to bf16x2 word: f0 -> low half, f1 -> high half
__device__ __forceinline__ uint32_t cvt2_bf16(float f0, float f1) {
    uint32_t r;
    asm("cvt.rn.bf16x2.f32 %0, %2, %1;" : "=r"(r) : "f"(f0), "f"(f1));
    return r;
}
__device__ __forceinline__ float bf16lo_f(uint32_t w) { return __uint_as_float(w << 16); }
__device__ __forceinline__ float bf16hi_f(uint32_t w) { return __uint_as_float(w & 0xffff0000u); }

// split one f32 pair into (hi, lo) bf16x2 words
__device__ __forceinline__ uint2 split2(float f0, float f1) {
    const uint32_t h = cvt2_bf16(f0, f1);
    return make_uint2(h, cvt2_bf16(f0 - bf16lo_f(h), f1 - bf16hi_f(h)));
}

// tf32 m16n8k8 mma (attention)
__device__ __forceinline__ void mma8(float& c0, float& c1, float& c2, float& c3,
                                     uint32_t a0, uint32_t a1, uint32_t a2, uint32_t a3,
                                     uint32_t b0, uint32_t b1) {
    asm volatile(
        "mma.sync.aligned.m16n8k8.row.col.f32.tf32.tf32.f32 "
        "{%0,%1,%2,%3}, {%4,%5,%6,%7}, {%8,%9}, {%0,%1,%2,%3};\n"
        : "+f"(c0), "+f"(c1), "+f"(c2), "+f"(c3)
        : "r"(a0), "r"(a1), "r"(a2), "r"(a3), "r"(b0), "r"(b1));
}

// bf16 m16n8k16 mma (projections)
__device__ __forceinline__ void mma16(float& c0, float& c1, float& c2, float& c3,
                                      uint32_t a0, uint32_t a1, uint32_t a2, uint32_t a3,
                                      uint32_t b0, uint32_t b1) {
    asm volatile(
        "mma.sync.aligned.m16n8k16.row.col.f32.bf16.bf16.f32 "
        "{%0,%1,%2,%3}, {%4,%5,%6,%7}, {%8,%9}, {%0,%1,%2,%3};\n"
        : "+f"(c0), "+f"(c1), "+f"(c2), "+f"(c3)
        : "r"(a0), "r"(a1), "r"(a2), "r"(a3), "r"(b0), "r"(b1));
}

// scatter one QKV element: Q pre-scaled tf32, K tf32, V tf32 TRANSPOSED
__device__ __forceinline__ void scatter_qkv(float v, int row, int col) {
    const int bb = row >> 11, nn = row & 2047;
    const int which = col / DIM;
    const int rem = col - which * DIM;
    const int head = rem >> 6, dd = rem & 63;
    if (which == 0)
        g_q[((size_t)((bb * HEADS + head) * SEQ + nn) << 6) + dd] = cvt_tf32(v * SCALE);
    else if (which == 1)
        g_k[((size_t)((bb * HEADS + head) * SEQ + nn) << 6) + dd] = cvt_tf32(v);
    else
        g_v[((size_t)((bb * HEADS + head) * DH + dd) << 11) + nn] = cvt_tf32(v);
}

// ---------------------------------------------------------------------------
// Split-bf16 (3-term) GEMMs. Block 128x64, BK=16, 256 threads, 8 warps as
// 4M x 2N, warp tile 32x32; hi/lo interleaved per k-pair; double-buffered.
// NON-TEMPLATED twin kernels; qkv converts A/B on the fly (R14-proven),
// out-GEMM reads packed A from g_attp and converts only B.
// ---------------------------------------------------------------------------
constexpr int PST = 24;   // words per row: 8 kpairs * 2 (hi,lo) + 8 pad

__global__ __launch_bounds__(256)
void gemm_qkv_bf16(const float* __restrict__ A, const float* __restrict__ W,
                   const float* __restrict__ bias)
{
    __shared__ __align__(16) uint32_t AS[2][128 * PST];
    __shared__ __align__(16) uint32_t BS[2][64 * PST];

    const int tid = threadIdx.x;
    const int lane = tid & 31;
    const int gid = lane >> 2, tig = lane & 3;
    const int w = tid >> 5;
    const int wm = w >> 1;
    const int wn = w & 1;
    const int rowBase = blockIdx.y * 128;
    const int colBase = blockIdx.x * 64;

    const int l_row  = tid >> 1;          // A loader row 0..127
    const int l_kp   = (tid & 1) * 4;     // A loader kpair base 0 or 4
    const int l_rowB = tid >> 2;          // B loader row 0..63
    const int l_kpB  = (tid & 3) * 2;     // B loader kpair base 0,2,4,6

    float4 acc[8];
    #pragma unroll
    for (int t = 0; t < 8; t++) acc[t] = make_float4(0.f, 0.f, 0.f, 0.f);

    const float* Aptr = A + (size_t)(rowBase + l_row) * DIM + l_kp * 2;
    const float* Bptr = W + (size_t)(colBase + l_rowB) * DIM + l_kpB * 2;

    float4 pa0 = *(const float4*)(Aptr);
    float4 pa1 = *(const float4*)(Aptr + 4);
    float4 pb0 = *(const float4*)(Bptr);

    {
        const int ab = l_row * PST + l_kp * 2;
        *(uint2*)&AS[0][ab + 0] = split2(pa0.x, pa0.y);
        *(uint2*)&AS[0][ab + 2] = split2(pa0.z, pa0.w);
        *(uint2*)&AS[0][ab + 4] = split2(pa1.x, pa1.y);
        *(uint2*)&AS[0][ab + 6] = split2(pa1.z, pa1.w);
        const int bb2 = l_rowB * PST + l_kpB * 2;
        *(uint2*)&BS[0][bb2 + 0] = split2(pb0.x, pb0.y);
        *(uint2*)&BS[0][bb2 + 2] = split2(pb0.z, pb0.w);
    }

    int cur = 0;
    for (int k0 = 0; k0 < DIM; k0 += 16) {
        __syncthreads();
        const bool more = (k0 + 16 < DIM);
        if (more) {
            pa0 = *(const float4*)(Aptr + k0 + 16);
            pa1 = *(const float4*)(Aptr + k0 + 20);
            pb0 = *(const float4*)(Bptr + k0 + 16);
        }
        uint2 q0[4], q1[4];
        #pragma unroll
        for (int j = 0; j < 4; j++) {
            const int cb = (wn * 32 + j * 8 + gid) * PST + tig * 2;
            q0[j] = *(const uint2*)&BS[cur][cb];
            q1[j] = *(const uint2*)&BS[cur][cb + 8];
        }
        #pragma unroll
        for (int i = 0; i < 2; i++) {
            const int r0 = (wm * 32 + i * 16 + gid) * PST + tig * 2;
            const int r1 = r0 + 8 * PST;
            const uint2 p00 = *(const uint2*)&AS[cur][r0];       // kpair tig
            const uint2 p01 = *(const uint2*)&AS[cur][r0 + 8];   // kpair tig+4
            const uint2 p10 = *(const uint2*)&AS[cur][r1];
            const uint2 p11 = *(const uint2*)&AS[cur][r1 + 8];
            #pragma unroll
            for (int j = 0; j < 4; j++) {
                const int t = i * 4 + j;
                mma16(acc[t].x, acc[t].y, acc[t].z, acc[t].w,
                      p00.x, p10.x, p01.x, p11.x, q0[j].x, q1[j].x);   // hi*hi
                mma16(acc[t].x, acc[t].y, acc[t].z, acc[t].w,
                      p00.x, p10.x, p01.x, p11.x, q0[j].y, q1[j].y);   // hi*lo
                mma16(acc[t].x, acc[t].y, acc[t].z, acc[t].w,
                      p00.y, p10.y, p01.y, p11.y, q0[j].x, q1[j].x);   // lo*hi
            }
        }
        if (more) {
            const int nxt = cur ^ 1;
            const int ab = l_row * PST + l_kp * 2;
            *(uint2*)&AS[nxt][ab + 0] = split2(pa0.x, pa0.y);
            *(uint2*)&AS[nxt][ab + 2] = split2(pa0.z, pa0.w);
            *(uint2*)&AS[nxt][ab + 4] = split2(pa1.x, pa1.y);
            *(uint2*)&AS[nxt][ab + 6] = split2(pa1.z, pa1.w);
            const int bb2 = l_rowB * PST + l_kpB * 2;
            *(uint2*)&BS[nxt][bb2 + 0] = split2(pb0.x, pb0.y);
            *(uint2*)&BS[nxt][bb2 + 2] = split2(pb0.z, pb0.w);
        }
        cur ^= 1;
    }

    #pragma unroll
    for (int i = 0; i < 2; i++) {
        const int r0 = rowBase + wm * 32 + i * 16 + gid;
        #pragma unroll
        for (int j = 0; j < 4; j++) {
            const int t = i * 4 + j;
            const int c0 = colBase + wn * 32 + j * 8 + tig * 2;
            const float b0v = bias[c0], b1v = bias[c0 + 1];
            scatter_qkv(acc[t].x + b0v, r0,     c0);
            scatter_qkv(acc[t].y + b1v, r0,     c0 + 1);
            scatter_qkv(acc[t].z + b0v, r0 + 8, c0);
            scatter_qkv(acc[t].w + b1v, r0 + 8, c0 + 1);
        }
    }
}

__global__ __launch_bounds__(256)
void gemm_out_bf16(const float* __restrict__ W, const float* __restrict__ bias,
                   float* __restrict__ out)
{
    __shared__ __align__(16) uint32_t AS[2][128 * PST];
    __shared__ __align__(16) uint32_t BS[2][64 * PST];

    const int tid = threadIdx.x;
    const int lane = tid & 31;
    const int gid = lane >> 2, tig = lane & 3;
    const int w = tid >> 5;
    const int wm = w >> 1;
    const int wn = w & 1;
    const int rowBase = blockIdx.y * 128;
    const int colBase = blockIdx.x * 64;

    const int l_row  = tid >> 1;          // A loader row, packed kpairs
    const int l_kp   = (tid & 1) * 4;
    const int l_rowB = tid >> 2;          // B loader row, raw floats
    const int l_kpB  = (tid & 3) * 2;

    float4 acc[8];
    #pragma unroll
    for (int t = 0; t < 8; t++) acc[t] = make_float4(0.f, 0.f, 0.f, 0.f);

    const uint2* Aptr = g_attp + (size_t)(rowBase + l_row) * KP + l_kp;
    const float* Bptr = W + (size_t)(colBase + l_rowB) * DIM + l_kpB * 2;

    uint4 ua0 = *(const uint4*)(Aptr);
    uint4 ua1 = *(const uint4*)(Aptr + 2);
    float4 pb0 = *(const float4*)(Bptr);

    {
        *(uint4*)&AS[0][l_row * PST + l_kp * 2]     = ua0;
        *(uint4*)&AS[0][l_row * PST + l_kp * 2 + 4] = ua1;
        const int bb2 = l_rowB * PST + l_kpB * 2;
        *(uint2*)&BS[0][bb2 + 0] = split2(pb0.x, pb0.y);
        *(uint2*)&BS[0][bb2 + 2] = split2(pb0.z, pb0.w);
    }

    int cur = 0;
    for (int k0 = 0; k0 < DIM; k0 += 16) {
        __syncthreads();
        const bool more = (k0 + 16 < DIM);
        if (more) {
            const int kb = (k0 + 16) >> 1;
            ua0 = *(const uint4*)(Aptr + kb);
            ua1 = *(const uint4*)(Aptr + kb + 2);
            pb0 = *(const float4*)(Bptr + k0 + 16);
        }
        uint2 q0[4], q1[4];
        #pragma unroll
        for (int j = 0; j < 4; j++) {
            const int cb = (wn * 32 + j * 8 + gid) * PST + tig * 2;
            q0[j] = *(const uint2*)&BS[cur][cb];
            q1[j] = *(const uint2*)&BS[cur][cb + 8];
        }
        #pragma unroll
        for (int i = 0; i < 2; i++) {
            const int r0 = (wm * 32 + i * 16 + gid) * PST + tig * 2;
            const int r1 = r0 + 8 * PST;
            const uint2 p00 = *(const uint2*)&AS[cur][r0];
            const uint2 p01 = *(const uint2*)&AS[cur][r0 + 8];
            const uint2 p10 = *(const uint2*)&AS[cur][r1];
            const uint2 p11 = *(const uint2*)&AS[cur][r1 + 8];
            #pragma unroll
            for (int j = 0; j < 4; j++) {
                const int t = i * 4 + j;
                mma16(acc[t].x, acc[t].y, acc[t].z, acc[t].w,
                      p00.x, p10.x, p01.x, p11.x, q0[j].x, q1[j].x);
                mma16(acc[t].x, acc[t].y, acc[t].z, acc[t].w,
                      p00.x, p10.x, p01.x, p11.x, q0[j].y, q1[j].y);
                mma16(acc[t].x, acc[t].y, acc[t].z, acc[t].w,
                      p00.y, p10.y, p01.y, p11.y, q0[j].x, q1[j].x);
            }
        }
        if (more) {
            const int nxt = cur ^ 1;
            *(uint4*)&AS[nxt][l_row * PST + l_kp * 2]     = ua0;
            *(uint4*)&AS[nxt][l_row * PST + l_kp * 2 + 4] = ua1;
            const int bb2 = l_rowB * PST + l_kpB * 2;
            *(uint2*)&BS[nxt][bb2 + 0] = split2(pb0.x, pb0.y);
            *(uint2*)&BS[nxt][bb2 + 2] = split2(pb0.z, pb0.w);
        }
        cur ^= 1;
    }

    #pragma unroll
    for (int i = 0; i < 2; i++) {
        const int r0 = rowBase + wm * 32 + i * 16 + gid;
        #pragma unroll
        for (int j = 0; j < 4; j++) {
            const int t = i * 4 + j;
            const int c0 = colBase + wn * 32 + j * 8 + tig * 2;
            const float b0v = bias[c0], b1v = bias[c0 + 1];
            out[(size_t)r0 * DIM + c0]           = acc[t].x + b0v;
            out[(size_t)r0 * DIM + c0 + 1]       = acc[t].y + b1v;
            out[(size_t)(r0 + 8) * DIM + c0]     = acc[t].z + b0v;
            out[(size_t)(r0 + 8) * DIM + c0 + 1] = acc[t].w + b1v;
        }
    }
}

// ---------------------------------------------------------------------------
// Flash attention, tf32 mma. Q/K/V already tf32 in global (Q pre-scaled,
// V transposed [b,h,d,n]). QS/KS/PS/VT all pair-permuted -> every fragment
// load (QK A/B, PV A/B) is one LDS.64. Epilogue writes split-bf16 packed
// output into g_attp for the out-projection.
// ---------------------------------------------------------------------------
constexpr int BC = 64;
constexpr int AST = 72;
constexpr int ATTN_SMEM = (128 + 64 + 64 + 128) * AST * 4;   // 110592 B

__global__ __launch_bounds__(256)
void attn_kernel()
{
    extern __shared__ uint32_t smu[];
    uint32_t* QS = smu;                 // [128][AST] permuted (q rows)
    uint32_t* KS = QS + 128 * AST;      // [64][AST]  permuted (key rows)
    uint32_t* VT = KS + 64 * AST;       // [64][AST]  permuted (d rows, keys)
    uint32_t* PS = VT + 64 * AST;       // [128][AST] permuted

    const int bh = blockIdx.x;
    const int qt = blockIdx.y;
    const int tid = threadIdx.x;
    const int lane = tid & 31;
    const int gid = lane >> 2, tig = lane & 3;
    const int w = tid >> 5;
    const int rb = w * 16;

    const uint4* Qg4 = (const uint4*)(g_q + (size_t)bh * SEQ * DH + (size_t)qt * 128 * DH);
    const uint32_t* Kg = g_k + (size_t)bh * SEQ * DH;
    const uint32_t* Vg = g_v + (size_t)bh * DH * SEQ;   // transposed [d][n]

    // Q tile: pure copy + permute (already scaled + tf32)
    for (int idx = tid; idx < 128 * DH / 4; idx += 256) {
        const int row = idx >> 4, c4 = (idx & 15) * 4;
        const int base = row * AST + (c4 & ~7) + ((c4 & 4) ? 1 : 0);
        uint4 v = Qg4[idx];
        QS[base + 0] = v.x;
        QS[base + 2] = v.y;
        QS[base + 4] = v.z;
        QS[base + 6] = v.w;
    }

    float4 o[8];
    #pragma unroll
    for (int j = 0; j < 8; j++) o[j] = make_float4(0.f, 0.f, 0.f, 0.f);
    float m0 = -3.0e38f, m1 = -3.0e38f;
    float l0 = 0.f, l1 = 0.f;

    const int pc0 = ((tig * 2) & 3) * 2 + (tig >> 1);
    const int pc1 = ((tig * 2 + 1) & 3) * 2 + (tig >> 1);

    for (int kt = 0; kt < SEQ / BC; kt++) {
        __syncthreads();
        // K tile: rows = keys, cols = d (permuted d-groups)
        const uint4* Kg4 = (const uint4*)(Kg + (size_t)kt * BC * DH);
        for (int idx = tid; idx < BC * DH / 4; idx += 256) {
            const int key = idx >> 4, c4 = (idx & 15) * 4;
            uint4 kv = Kg4[idx];
            const int kb = key * AST + (c4 & ~7) + ((c4 & 4) ? 1 : 0);
            KS[kb + 0] = kv.x;
            KS[kb + 2] = kv.y;
            KS[kb + 4] = kv.z;
            KS[kb + 6] = kv.w;
        }
        // V tile (transposed source): rows = d, cols = keys (permuted groups)
        for (int idx = tid; idx < DH * BC / 4; idx += 256) {
            const int d = idx >> 4, k4 = (idx & 15) * 4;
            uint4 vv = *(const uint4*)(Vg + (size_t)d * SEQ + kt * BC + k4);
            const int vb = d * AST + (k4 & ~7) + ((k4 & 4) ? 1 : 0);
            VT[vb + 0] = vv.x;
            VT[vb + 2] = vv.y;
            VT[vb + 4] = vv.z;
            VT[vb + 6] = vv.w;
        }
        __syncthreads();

        // S = Q * K^T : all fragments via LDS.64
        float4 s[8];
        #pragma unroll
        for (int j = 0; j < 8; j++) s[j] = make_float4(0.f, 0.f, 0.f, 0.f);
        #pragma unroll
        for (int kk = 0; kk < DH; kk += 8) {
            const uint2 pA0 = *(const uint2*)&QS[(rb + gid) * AST + kk + tig * 2];
            const uint2 pA1 = *(const uint2*)&QS[(rb + gid + 8) * AST + kk + tig * 2];
            #pragma unroll
            for (int j = 0; j < 8; j++) {
                const uint2 pB = *(const uint2*)&KS[(j * 8 + gid) * AST + kk + tig * 2];
                mma8(s[j].x, s[j].y, s[j].z, s[j].w,
                     pA0.x, pA1.x, pA0.y, pA1.y, pB.x, pB.y);
            }
        }

        float mt0 = -3.0e38f, mt1 = -3.0e38f;
        #pragma unroll
        for (int j = 0; j < 8; j++) {
            mt0 = fmaxf(mt0, fmaxf(s[j].x, s[j].y));
            mt1 = fmaxf(mt1, fmaxf(s[j].z, s[j].w));
        }
        mt0 = fmaxf(mt0, __shfl_xor_sync(0xffffffffu, mt0, 1));
        mt0 = fmaxf(mt0, __shfl_xor_sync(0xffffffffu, mt0, 2));
        mt1 = fmaxf(mt1, __shfl_xor_sync(0xffffffffu, mt1, 1));
        mt1 = fmaxf(mt1, __shfl_xor_sync(0xffffffffu, mt1, 2));
        const float mn0 = fmaxf(m0, mt0), mn1 = fmaxf(m1, mt1);
        const float al0 = __expf(m0 - mn0), al1 = __expf(m1 - mn1);
        m0 = mn0; m1 = mn1;

        float rs0 = 0.f, rs1 = 0.f;
        const int p0base = (rb + gid) * AST;
        const int p1base = (rb + gid + 8) * AST;
        #pragma unroll
        for (int j = 0; j < 8; j++) {
            const float e0 = __expf(s[j].x - mn0);
            const float e1 = __expf(s[j].y - mn0);
            const float e2 = __expf(s[j].z - mn1);
            const float e3 = __expf(s[j].w - mn1);
            rs0 += e0 + e1; rs1 += e2 + e3;
            PS[p0base + j * 8 + pc0] = cvt_tf32(e0);
            PS[p0base + j * 8 + pc1] = cvt_tf32(e1);
            PS[p1base + j * 8 + pc0] = cvt_tf32(e2);
            PS[p1base + j * 8 + pc1] = cvt_tf32(e3);
        }
        rs0 += __shfl_xor_sync(0xffffffffu, rs0, 1);
        rs0 += __shfl_xor_sync(0xffffffffu, rs0, 2);
        rs1 += __shfl_xor_sync(0xffffffffu, rs1, 1);
        rs1 += __shfl_xor_sync(0xffffffffu, rs1, 2);
        l0 = l0 * al0 + rs0;
        l1 = l1 * al1 + rs1;

        #pragma unroll
        for (int j = 0; j < 8; j++) {
            o[j].x *= al0; o[j].y *= al0;
            o[j].z *= al1; o[j].w *= al1;
        }
        __syncwarp();

        // O += P * V : both operands via LDS.64 (VT rows = d, keys permuted)
        #pragma unroll
        for (int kk = 0; kk < BC; kk += 8) {
            const uint2 pA0 = *(const uint2*)&PS[(rb + gid) * AST + kk + tig * 2];
            const uint2 pA1 = *(const uint2*)&PS[(rb + gid + 8) * AST + kk + tig * 2];
            #pragma unroll
            for (int j = 0; j < 8; j++) {
                const uint2 pV = *(const uint2*)&VT[(j * 8 + gid) * AST + kk + tig * 2];
                mma8(o[j].x, o[j].y, o[j].z, o[j].w,
                     pA0.x, pA1.x, pA0.y, pA1.y, pV.x, pV.y);
            }
        }
    }

    // Normalize and write SPLIT-PACKED output to g_attp:
    // row = bb*SEQ + n, kpair = head*32 + j*4 + tig (cols j*8+tig*2, +1)
    const int bb = bh / HEADS;
    const int head = bh % HEADS;
    const float inv0 = 1.0f / l0, inv1 = 1.0f / l1;
    const int n0 = qt * 128 + rb + gid;
    const int n1 = n0 + 8;
    uint2* dst0 = g_attp + (size_t)(bb * SEQ + n0) * KP + head * 32;
    uint2* dst1 = g_attp + (size_t)(bb * SEQ + n1) * KP + head * 32;
    #pragma unroll
    for (int j = 0; j < 8; j++) {
        dst0[j * 4 + tig] = split2(o[j].x * inv0, o[j].y * inv0);
        dst1[j * 4 + tig] = split2(o[j].z * inv1, o[j].w * inv1);
    }
}

// ---------------------------------------------------------------------------
// Launch
// ---------------------------------------------------------------------------
extern "C" void kernel_launch(void* const* d_in, const int* in_sizes, int n_in,
                              void* d_out, int out_size)
{
    const float* x     = (const float*)d_in[0];
    const float* w_qkv = (const float*)d_in[1];
    const float* b_qkv = (const float*)d_in[2];
    const float* w_out = (const float*)d_in[3];
    const float* b_out = (const float*)d_in[4];
    float* out = (float*)d_out;

    cudaFuncSetAttribute(attn_kernel,
                         cudaFuncAttributeMaxDynamicSharedMemorySize, ATTN_SMEM);

    // 1) QKV projection (split-bf16 TC; epilogue emits tf32 Q/K + transposed V)
    dim3 g1(3 * DIM / 64, MROWS / 128);   // (36, 64)
    gemm_qkv_bf16<<<g1, 256>>>(x, w_qkv, b_qkv);

    // 2) Flash attention (tf32 TC; writes packed output into g_attp)
    dim3 g2(BATCH * HEADS, SEQ / 128);    // (48, 16)
    attn_kernel<<<g2, 256, ATTN_SMEM>>>();

    // 3) Output projection (split-bf16 TC; A preconverted in g_attp)
    dim3 g3(DIM / 64, MROWS / 128);       // (12, 64)
    gemm_out_bf16<<<g3, 256>>>(w_out, b_out, out);
}